// round 7
// baseline (speedup 1.0000x reference)
#include <cuda_runtime.h>
#include <math.h>
#include <stdint.h>

#define DM 512
#define NH 8
#define ED 64
#define NB 2
#define SL 2048
#define MT (NB*SL)          // 4096 rows
#define NBH (NB*NH)         // 16 sequences
#define CK 128              // chunk length
#define NCH (SL/CK)         // 16 chunks

// ---------------- scratch (static device globals; no runtime alloc) --------
__device__ float g_q[MT*DM];
__device__ float g_k[MT*DM];
__device__ float g_v[MT*DM];
__device__ float g_attn[MT*DM];
__device__ float g_y[MT*DM];
__device__ float g_WqkvT[3*DM*DM];   // [1536][512], tf32-rounded
__device__ float g_WoutT[DM*DM];     // [512][512],  tf32-rounded
__device__ float g_Sloc[NBH*NCH*ED*ED];
__device__ float g_Sin [NBH*NCH*ED*ED];   // row-major carry-in states [e][f]
__device__ float g_zloc[NBH*NCH*ED];
__device__ float g_zin [NBH*NCH*ED];

__device__ __forceinline__ float lam_of(const float* dl, int h){
    return 0.99f + 0.01f/(1.0f + expf(-dl[h]));
}
__device__ __forceinline__ uint32_t f2tf32(float x){
    uint32_t r; asm("cvt.rna.tf32.f32 %0, %1;" : "=r"(r) : "f"(x)); return r;
}
__device__ __forceinline__ float round_tf32(float x){
    return __uint_as_float(f2tf32(x));
}
__device__ __forceinline__ void mma_tf32(float* c, const uint4& a, const uint2& b){
    asm volatile("mma.sync.aligned.m16n8k8.row.col.f32.tf32.tf32.f32 "
        "{%0,%1,%2,%3}, {%4,%5,%6,%7}, {%8,%9}, {%0,%1,%2,%3};"
        : "+f"(c[0]), "+f"(c[1]), "+f"(c[2]), "+f"(c[3])
        : "r"(a.x), "r"(a.y), "r"(a.z), "r"(a.w), "r"(b.x), "r"(b.y));
}
// fragment-pack index helpers (m16n8k8 tf32)
__device__ __forceinline__ int Aidx(int KS, int r, int k){
    return (((r>>4)*KS + (k>>3))*32 + (r&7)*4 + (k&3))*4 + ((r>>3)&1) + 2*((k>>2)&1);
}
__device__ __forceinline__ int Bidx(int KS, int n, int k){
    return (((n>>3)*KS + (k>>3))*32 + (n&7)*4 + (k&3))*2 + ((k>>2)&1);
}

// ------- fused W transpose + tf32 pre-round: Wt[n][k] = round(W[k][n]) ------
__global__ void transpose_kernel(const float* __restrict__ Wq,
                                 const float* __restrict__ Wo)
{
    __shared__ float tile[32][33];
    int bx = blockIdx.x;
    const float* W; float* Wt; int N;
    if (bx < 48){ W = Wq; Wt = g_WqkvT; N = 3*DM; }
    else        { bx -= 48; W = Wo; Wt = g_WoutT; N = DM; }
    const int n0 = bx*32, k0 = blockIdx.y*32;
    const int tx = threadIdx.x, ty = threadIdx.y;   // 32 x 8
    #pragma unroll
    for (int j=0;j<32;j+=8)
        tile[ty+j][tx] = W[(size_t)(k0+ty+j)*N + n0+tx];
    __syncthreads();
    #pragma unroll
    for (int j=0;j<32;j+=8)
        Wt[(size_t)(n0+ty+j)*DM + k0+tx] = round_tf32(tile[tx][ty+j]);
}

// =================== tf32 mma.sync GEMM: D = A @ Wt^T + b ===================
// MODE 0: qkv = x @ W_qkv + b (epilogue: ELU maps, split q/k/v, tf32-rounded out)
// MODE 1: y   = attn @ W_out + b (A already tf32-rounded)
template<int MODE>
__global__ __launch_bounds__(256) void mma_gemm_kernel(const float* __restrict__ Ain,
                                                       const float* __restrict__ bias)
{
    extern __shared__ uint32_t sm[];        // 2 bufs x (A 4096 + B 4096) u32
    const float* A  = (MODE==0) ? Ain : g_attn;
    const float* Wt = (MODE==0) ? g_WqkvT : g_WoutT;
    const int m0 = blockIdx.y*128, n0 = blockIdx.x*128;
    const int t = threadIdx.x, lane = t&31, wid = t>>5;
    const int wm = wid&1, wn = wid>>1;

    const int c4    = (t&7)<<2;
    const int kkL   = c4>>3;
    const int cregL = (c4>>2)&1;
    const int rlo   = t>>3;
    const int lane0 = (rlo&7)<<2;
    const int rhi   = (t>>6)&1;
    const int mt0   = t>>7;
    const int nt0   = (t>>6)&3;
    const int regA  = rhi + 2*cregL;

    float4 ra[4], rb[4];
    float acc[4][4][4];
    #pragma unroll
    for (int i=0;i<4;i++)
        #pragma unroll
        for (int j=0;j<4;j++)
            #pragma unroll
            for (int r=0;r<4;r++) acc[i][j][r]=0.f;

    auto ldg = [&](int c){
        const int k0 = c*32;
        #pragma unroll
        for (int i=0;i<4;i++){
            ra[i] = *(const float4*)&A [(size_t)(m0 + rlo + 32*i)*DM + k0 + c4];
            rb[i] = *(const float4*)&Wt[(size_t)(n0 + rlo + 32*i)*DM + k0 + c4];
        }
    };
    auto cvtA = [&](float x)->uint32_t {
        return (MODE==0) ? f2tf32(x) : __float_as_uint(x);
    };
    auto sts = [&](int buf){
        uint32_t* Ab = sm + buf*8192;
        uint32_t* Bb = Ab + 4096;
        #pragma unroll
        for (int i=0;i<4;i++){
            const int mt = mt0 + 2*i;
            const uint32_t ab = (uint32_t)(((mt*4 + kkL)*32 + lane0)*4 + regA);
            Ab[ab + 0*4] = cvtA(ra[i].x);
            Ab[ab + 1*4] = cvtA(ra[i].y);
            Ab[ab + 2*4] = cvtA(ra[i].z);
            Ab[ab + 3*4] = cvtA(ra[i].w);
            const int nt = nt0 + 4*i;
            const uint32_t bb = (uint32_t)(((nt*4 + kkL)*32 + lane0)*2 + cregL);
            Bb[bb + 0*2] = __float_as_uint(rb[i].x);
            Bb[bb + 1*2] = __float_as_uint(rb[i].y);
            Bb[bb + 2*2] = __float_as_uint(rb[i].z);
            Bb[bb + 3*2] = __float_as_uint(rb[i].w);
        }
    };
    auto compute = [&](int buf){
        const uint32_t* Ab = sm + buf*8192;
        const uint32_t* Bb = Ab + 4096;
        #pragma unroll
        for (int kk=0;kk<4;kk++){
            uint4 a[4]; uint2 b[4];
            #pragma unroll
            for (int i=0;i<4;i++)
                a[i] = *(const uint4*)&Ab[(((wm*4+i)*4+kk)*32 + lane)*4];
            #pragma unroll
            for (int j=0;j<4;j++)
                b[j] = *(const uint2*)&Bb[(((wn*4+j)*4+kk)*32 + lane)*2];
            #pragma unroll
            for (int i=0;i<4;i++)
                #pragma unroll
                for (int j=0;j<4;j++)
                    mma_tf32(acc[i][j], a[i], b[j]);
        }
    };

    ldg(0); sts(0); __syncthreads();
    #pragma unroll 1
    for (int c=0;c<16;c++){
        if (c<15) ldg(c+1);
        compute(c&1);
        if (c<15) sts((c+1)&1);
        __syncthreads();
    }

    int regi = 0; float* dst;
    if (MODE==0){
        regi = n0 >> 9;
        dst = (regi==0) ? g_q : (regi==1) ? g_k : g_v;
    } else dst = g_y;
    const int nsub = (MODE==0) ? (n0 - regi*512) : n0;
    const int rowl = lane>>2, colp = (lane&3)*2;

    #pragma unroll
    for (int i=0;i<4;i++){
        #pragma unroll
        for (int j=0;j<4;j++){
            const int nn = n0   + wn*32 + j*8 + colp;
            const int nc = nsub + wn*32 + j*8 + colp;
            const float b0v = __ldg(&bias[nn]);
            const float b1v = __ldg(&bias[nn+1]);
            float v[4] = { acc[i][j][0] + b0v, acc[i][j][1] + b1v,
                           acc[i][j][2] + b0v, acc[i][j][3] + b1v };
            if (MODE==0){
                if (regi==0){
                    #pragma unroll
                    for (int e=0;e<4;e++){ float x=(v[e]>0.f)?v[e]+1.f:expf(v[e]); v[e]=round_tf32(x*0.125f); }
                } else if (regi==1){
                    #pragma unroll
                    for (int e=0;e<4;e++){ float x=(v[e]>0.f)?v[e]+1.f:expf(v[e]); v[e]=round_tf32(x); }
                } else {
                    #pragma unroll
                    for (int e=0;e<4;e++) v[e]=round_tf32(v[e]);
                }
            }
            const int r0 = m0 + wm*64 + i*16 + rowl;
            *(float2*)&dst[(size_t)r0*DM + nc]     = make_float2(v[0], v[1]);
            *(float2*)&dst[(size_t)(r0+8)*DM + nc] = make_float2(v[2], v[3]);
        }
    }
}

// ============== chunk_local via mma: S_loc = (pw*K)^T @ V,  64x64x128 =======
// direct GMEM->fragment pack, parallel z reduction, 66KB smem (3 CTA/SM)
__global__ __launch_bounds__(256) void chunk_local_kernel(const float* __restrict__ dl)
{
    extern __shared__ uint32_t sl[];
    uint32_t* Aa = sl;            // A-pack 64x128 (KS=16) : 8192 u32
    uint32_t* Bb = sl + 8192;     // B-pack 64x128 (KS=16) : 8192 u32
    __shared__ float pw[128];
    __shared__ float zpart[4][64];

    const int c = blockIdx.x, bh = blockIdx.y;
    const int b = bh / NH, h = bh % NH;
    const int t = threadIdx.x, lane = t&31, wid = t>>5;
    const int wm = wid&1, wn = wid>>1;
    const int g = lane>>2, tg = lane&3;
    const float lam = lam_of(dl, h);
    if (t < 128) pw[t] = exp2f((float)t * log2f(lam));
    __syncthreads();

    const size_t rowbase = ((size_t)b*SL + (size_t)c*CK)*DM + h*ED;
    // direct pack: A[e][j] = round(pw[127-j]*K[j][e]); B[f][j] = V[j][f] (pre-rounded)
    for (int vi = t; vi < 2048; vi += 256){
        const int j = vi >> 4, e4 = (vi & 15)*4;
        const float w = pw[127-j];
        float4 kv = *(const float4*)&g_k[rowbase + (size_t)j*DM + e4];
        Aa[Aidx(16, e4+0, j)] = f2tf32(w*kv.x);
        Aa[Aidx(16, e4+1, j)] = f2tf32(w*kv.y);
        Aa[Aidx(16, e4+2, j)] = f2tf32(w*kv.z);
        Aa[Aidx(16, e4+3, j)] = f2tf32(w*kv.w);
        float4 vv = *(const float4*)&g_v[rowbase + (size_t)j*DM + e4];
        Bb[Bidx(16, e4+0, j)] = __float_as_uint(vv.x);
        Bb[Bidx(16, e4+1, j)] = __float_as_uint(vv.y);
        Bb[Bidx(16, e4+2, j)] = __float_as_uint(vv.z);
        Bb[Bidx(16, e4+3, j)] = __float_as_uint(vv.w);
    }
    // z partials: z[e] = sum_j pw[127-j]*k[j][e], split 4 ways over j
    {
        const int e = t & 63, part = t >> 6;
        float z = 0.f;
        #pragma unroll 4
        for (int j = part*32; j < part*32+32; j++)
            z += pw[127-j] * g_k[rowbase + (size_t)j*DM + e];
        zpart[part][e] = z;
    }
    __syncthreads();
    if (t < ED)
        g_zloc[((size_t)bh*NCH + c)*ED + t] =
            zpart[0][t] + zpart[1][t] + zpart[2][t] + zpart[3][t];

    float acc[2][2][4];
    #pragma unroll
    for (int i=0;i<2;i++)
        #pragma unroll
        for (int j=0;j<2;j++)
            #pragma unroll
            for (int r=0;r<4;r++) acc[i][j][r]=0.f;
    #pragma unroll
    for (int kk=0;kk<16;kk++){
        uint4 a[2]; uint2 b2[2];
        #pragma unroll
        for (int i=0;i<2;i++)
            a[i] = *(const uint4*)&Aa[(((wm*2+i)*16+kk)*32 + lane)*4];
        #pragma unroll
        for (int j=0;j<2;j++)
            b2[j] = *(const uint2*)&Bb[(((wn*2+j)*16+kk)*32 + lane)*2];
        #pragma unroll
        for (int i=0;i<2;i++)
            #pragma unroll
            for (int j=0;j<2;j++)
                mma_tf32(acc[i][j], a[i], b2[j]);
    }
    const size_t sb = ((size_t)bh*NCH + c)*ED*ED;
    #pragma unroll
    for (int i=0;i<2;i++){
        #pragma unroll
        for (int j=0;j<2;j++){
            const int e0 = wm*32 + i*16 + g;
            const int f0 = wn*16 + j*8 + tg*2;
            *(float2*)&g_Sloc[sb + e0*ED + f0]     = make_float2(acc[i][j][0], acc[i][j][1]);
            *(float2*)&g_Sloc[sb + (e0+8)*ED + f0] = make_float2(acc[i][j][2], acc[i][j][3]);
        }
    }
}

// ---------------- inter-chunk prefix scan (row-major, coalesced) -----------
__global__ __launch_bounds__(256) void scan_kernel(const float* __restrict__ dl)
{
    const int bh = blockIdx.x;
    const int h = bh % NH;
    const int t = threadIdx.x;
    const float lam  = lam_of(dl, h);
    const float lamC = exp2f((float)CK * log2f(lam));
    float s[16];
    #pragma unroll
    for (int i=0;i<16;i++) s[i]=0.f;
    float z = 0.f;
    for (int c = 0; c < NCH; c++){
        const size_t base = ((size_t)bh*NCH + c)*ED*ED + (size_t)t*16;
        #pragma unroll
        for (int i=0;i<16;i+=4)
            *(float4*)&g_Sin[base+i] = make_float4(s[i],s[i+1],s[i+2],s[i+3]);
        if (t < ED) g_zin[((size_t)bh*NCH+c)*ED + t] = z;
        #pragma unroll
        for (int i=0;i<16;i+=4){
            float4 lv = *(const float4*)&g_Sloc[base+i];
            s[i]   = lamC*s[i]   + lv.x;
            s[i+1] = lamC*s[i+1] + lv.y;
            s[i+2] = lamC*s[i+2] + lv.z;
            s[i+3] = lamC*s[i+3] + lv.w;
        }
        if (t < ED) z = lamC*z + g_zloc[((size_t)bh*NCH+c)*ED + t];
    }
}

// ================= chunk_out via mma =======================================
__global__ __launch_bounds__(256) void chunk_out_kernel(const float* __restrict__ dl)
{
    extern __shared__ uint32_t su[];
    uint32_t* Qa = su;             // A-pack Q  128x64  (KS=8)  : 8192
    uint32_t* Kb = Qa + 8192;      // B-pack K  n=128,k=64      : 8192
    uint32_t* Pa = Kb + 8192;      // A-pack P  128x128 (KS=16) : 16384
    uint32_t* Vb = Pa + 16384;     // B-pack V^T n=64,k=128     : 8192
    uint32_t* Sb = Vb + 8192;      // B-pack S^T n=64,k=64      : 4096
    __shared__ float pw[132];
    __shared__ float dens2[4][128];
    __shared__ float dens[128];
    __shared__ float dq2[2][128];
    __shared__ float dqs[128];
    __shared__ float zs[64];

    const int c = blockIdx.x, bh = blockIdx.y;
    const int b = bh / NH, h = bh % NH;
    const int t = threadIdx.x, lane = t&31, wid = t>>5;
    const int wm = wid&1, wn = wid>>1;
    const int g = lane>>2, tg = lane&3;
    const float lam = lam_of(dl, h);
    if (t <= 128) pw[t] = exp2f((float)t * log2f(lam));
    if (t < ED)   zs[t] = g_zin[((size_t)bh*NCH+c)*ED + t];

    const size_t rowbase = ((size_t)b*SL + (size_t)c*CK)*DM + h*ED;
    // direct packs (q,k,v pre-rounded in GEMM epilogue -> raw bit copies)
    for (int idx = t; idx < 8192; idx += 256){
        const int r = idx >> 6, k = idx & 63;
        Qa[Aidx(8, r, k)] = __float_as_uint(g_q[rowbase + (size_t)r*DM + k]);
        Kb[Bidx(8, r, k)] = __float_as_uint(g_k[rowbase + (size_t)r*DM + k]);
        Vb[Bidx(16, idx & 63, idx >> 6)] = __float_as_uint(g_v[rowbase + (size_t)(idx>>6)*DM + (idx&63)]);
    }
    // pack S^T: B[n=f][k=e] = S_in[e][f]; coalesced LDG, scattered STS
    {
        const size_t sbase = ((size_t)bh*NCH + c)*ED*ED;
        for (int idx = t; idx < 4096; idx += 256){
            const int e = idx >> 6, f = idx & 63;
            Sb[Bidx(8, f, e)] = f2tf32(g_Sin[sbase + idx]);
        }
    }
    __syncthreads();

    // dqs partials: q_row . z_in, split over e halves (reads zs after sync)
    {
        const int row = t & 127, half = t >> 7;
        float q = 0.f;
        #pragma unroll 4
        for (int e = half*32; e < half*32+32; e++)
            q += g_q[rowbase + (size_t)row*DM + e] * zs[e];
        dq2[half][row] = q;
    }

    // phase 1: P = Q K^T
    float accP[4][4][4];
    #pragma unroll
    for (int i=0;i<4;i++)
        #pragma unroll
        for (int j=0;j<4;j++)
            #pragma unroll
            for (int r=0;r<4;r++) accP[i][j][r]=0.f;
    #pragma unroll
    for (int kk=0;kk<8;kk++){
        uint4 a[4]; uint2 b2[4];
        #pragma unroll
        for (int i=0;i<4;i++)
            a[i] = *(const uint4*)&Qa[(((wm*4+i)*8+kk)*32 + lane)*4];
        #pragma unroll
        for (int j=0;j<4;j++)
            b2[j] = *(const uint2*)&Kb[(((wn*4+j)*8+kk)*32 + lane)*2];
        #pragma unroll
        for (int i=0;i<4;i++)
            #pragma unroll
            for (int j=0;j<4;j++)
                mma_tf32(accP[i][j], a[i], b2[j]);
    }

    // stage B: weight+mask, repack P into A-frag layout; dens partials
    #pragma unroll
    for (int i=0;i<4;i++){
        float rs_lo = 0.f, rs_hi = 0.f;
        const int ii_lo = wm*64 + i*16 + g;
        const int ii_hi = ii_lo + 8;
        #pragma unroll
        for (int j=0;j<4;j++){
            #pragma unroll
            for (int r=0;r<4;r++){
                const int ii = (r<2) ? ii_lo : ii_hi;
                const int jj = wn*32 + j*8 + tg*2 + (r&1);
                const float w = (jj <= ii) ? pw[ii-jj] : 0.f;
                const float val = w * accP[i][j][r];
                Pa[Aidx(16, ii, jj)] = f2tf32(val);
                if (r<2) rs_lo += val; else rs_hi += val;
            }
        }
        rs_lo += __shfl_down_sync(0xffffffffu, rs_lo, 2, 4);
        rs_lo += __shfl_down_sync(0xffffffffu, rs_lo, 1, 4);
        rs_hi += __shfl_down_sync(0xffffffffu, rs_hi, 2, 4);
        rs_hi += __shfl_down_sync(0xffffffffu, rs_hi, 1, 4);
        if (tg == 0){
            dens2[wn][ii_lo] = rs_lo;
            dens2[wn][ii_hi] = rs_hi;
        }
    }
    __syncthreads();

    // combine (deterministic)
    if (t < 128){
        dens[t] = dens2[0][t] + dens2[1][t] + dens2[2][t] + dens2[3][t];
        dqs[t]  = dq2[0][t] + dq2[1][t];
    }

    // phase 3: acc1 = Q @ S_in (K=64), acc2 = P @ V (K=128)
    float acc1[4][2][4], acc2[4][2][4];
    #pragma unroll
    for (int i=0;i<4;i++)
        #pragma unroll
        for (int j=0;j<2;j++)
            #pragma unroll
            for (int r=0;r<4;r++){ acc1[i][j][r]=0.f; acc2[i][j][r]=0.f; }
    #pragma unroll
    for (int kk=0;kk<8;kk++){
        uint4 a[4]; uint2 b2[2];
        #pragma unroll
        for (int i=0;i<4;i++)
            a[i] = *(const uint4*)&Qa[(((wm*4+i)*8+kk)*32 + lane)*4];
        #pragma unroll
        for (int j=0;j<2;j++)
            b2[j] = *(const uint2*)&Sb[(((wn*2+j)*8+kk)*32 + lane)*2];
        #pragma unroll
        for (int i=0;i<4;i++)
            #pragma unroll
            for (int j=0;j<2;j++)
                mma_tf32(acc1[i][j], a[i], b2[j]);
    }
    #pragma unroll
    for (int kk=0;kk<16;kk++){
        uint4 a[4]; uint2 b2[2];
        #pragma unroll
        for (int i=0;i<4;i++)
            a[i] = *(const uint4*)&Pa[(((wm*4+i)*16+kk)*32 + lane)*4];
        #pragma unroll
        for (int j=0;j<2;j++)
            b2[j] = *(const uint2*)&Vb[(((wn*2+j)*16+kk)*32 + lane)*2];
        #pragma unroll
        for (int i=0;i<4;i++)
            #pragma unroll
            for (int j=0;j<2;j++)
                mma_tf32(acc2[i][j], a[i], b2[j]);
    }
    __syncthreads();   // dens/dqs ready for all

    // final: combine, divide, store (pre-rounded to tf32 for mode-1 GEMM)
    const int mrow = b*SL + c*CK;
    #pragma unroll
    for (int i=0;i<4;i++){
        const int ii_lo = wm*64 + i*16 + g;
        #pragma unroll
        for (int rr=0;rr<2;rr++){
            const int ii = ii_lo + rr*8;
            const float pwi = pw[ii+1];
            const float inv = 1.f / (pwi*dqs[ii] + dens[ii] + 1e-6f);
            #pragma unroll
            for (int j=0;j<2;j++){
                const int f0 = wn*16 + j*8 + tg*2;
                const float v0 = round_tf32((pwi*acc1[i][j][rr*2+0] + acc2[i][j][rr*2+0])*inv);
                const float v1 = round_tf32((pwi*acc1[i][j][rr*2+1] + acc2[i][j][rr*2+1])*inv);
                *(float2*)&g_attn[(size_t)(mrow+ii)*DM + h*ED + f0] = make_float2(v0, v1);
            }
        }
    }
}

// ---------------- LayerNorm ------------------------------------------------
__global__ __launch_bounds__(128) void ln_kernel(const float* __restrict__ gg,
                                                 const float* __restrict__ bb,
                                                 float* __restrict__ out)
{
    const int row = blockIdx.x, t = threadIdx.x;
    __shared__ float red[8];
    float4 v = *(const float4*)&g_y[(size_t)row*DM + t*4];
    float s  = v.x+v.y+v.z+v.w;
    float s2 = v.x*v.x+v.y*v.y+v.z*v.z+v.w*v.w;
    #pragma unroll
    for (int o=16;o;o>>=1){
        s  += __shfl_xor_sync(0xffffffffu, s,  o);
        s2 += __shfl_xor_sync(0xffffffffu, s2, o);
    }
    const int w = t>>5;
    if ((t&31)==0){ red[w]=s; red[4+w]=s2; }
    __syncthreads();
    s  = red[0]+red[1]+red[2]+red[3];
    s2 = red[4]+red[5]+red[6]+red[7];
    const float mean = s*(1.0f/DM);
    const float var  = s2*(1.0f/DM) - mean*mean;
    const float inv  = rsqrtf(var + 1e-5f);
    float4 gv = *(const float4*)&gg[t*4];
    float4 bv = *(const float4*)&bb[t*4];
    float4 o;
    o.x = (v.x-mean)*inv*gv.x + bv.x;
    o.y = (v.y-mean)*inv*gv.y + bv.y;
    o.z = (v.z-mean)*inv*gv.z + bv.z;
    o.w = (v.w-mean)*inv*gv.w + bv.w;
    *(float4*)&out[(size_t)row*DM + t*4] = o;
}

// ---------------- launch ----------------------------------------------------
extern "C" void kernel_launch(void* const* d_in, const int* in_sizes, int n_in,
                              void* d_out, int out_size)
{
    const float* x     = (const float*)d_in[0];
    const float* W_qkv = (const float*)d_in[1];
    const float* b_qkv = (const float*)d_in[2];
    const float* W_out = (const float*)d_in[3];
    const float* b_out = (const float*)d_in[4];
    const float* dl    = (const float*)d_in[5];
    const float* ln_g  = (const float*)d_in[6];
    const float* ln_b  = (const float*)d_in[7];
    float* out = (float*)d_out;

    const int smem_cl = 16384*4;                                  // 65536 B
    const int smem_co = 45056*4;                                  // 180224 B
    const int smem_mm = 2*8192*4;                                 // 65536 B
    cudaFuncSetAttribute(chunk_local_kernel,
                         cudaFuncAttributeMaxDynamicSharedMemorySize, smem_cl);
    cudaFuncSetAttribute(chunk_out_kernel,
                         cudaFuncAttributeMaxDynamicSharedMemorySize, smem_co);
    cudaFuncSetAttribute(mma_gemm_kernel<0>,
                         cudaFuncAttributeMaxDynamicSharedMemorySize, smem_mm);
    cudaFuncSetAttribute(mma_gemm_kernel<1>,
                         cudaFuncAttributeMaxDynamicSharedMemorySize, smem_mm);

    transpose_kernel<<<dim3(64,16), dim3(32,8)>>>(W_qkv, W_out);
    mma_gemm_kernel<0><<<dim3(12,32), 256, smem_mm>>>(x, b_qkv);
    chunk_local_kernel<<<dim3(NCH,NBH),256,smem_cl>>>(dl);
    scan_kernel<<<NBH,256>>>(dl);
    chunk_out_kernel<<<dim3(NCH,NBH),256,smem_co>>>(dl);
    mma_gemm_kernel<1><<<dim3(4,32), 256, smem_mm>>>(nullptr, b_out);
    ln_kernel<<<MT,128>>>(ln_g, ln_b, out);
}

// round 8
// speedup vs baseline: 1.0879x; 1.0879x over previous
#include <cuda_runtime.h>
#include <math.h>
#include <stdint.h>

#define DM 512
#define NH 8
#define ED 64
#define NB 2
#define SL 2048
#define MT (NB*SL)          // 4096 rows
#define NBH (NB*NH)         // 16 sequences
#define CK 128              // chunk length
#define NCH (SL/CK)         // 16 chunks

// ---------------- scratch (static device globals; no runtime alloc) --------
__device__ float g_q[MT*DM];
__device__ float g_k[MT*DM];
__device__ float g_v[MT*DM];
__device__ float g_attn[MT*DM];
__device__ float g_y[MT*DM];
__device__ float g_WqkvT[3*DM*DM];   // [1536][512], tf32-rounded
__device__ float g_WoutT[DM*DM];     // [512][512],  tf32-rounded
__device__ float g_Sloc[NBH*NCH*ED*ED];
__device__ float g_Sin [NBH*NCH*ED*ED];   // row-major carry-in states [e][f]
__device__ float g_zloc[NBH*NCH*ED];
__device__ float g_zin [NBH*NCH*ED];

__device__ __forceinline__ float lam_of(const float* dl, int h){
    return 0.99f + 0.01f/(1.0f + expf(-dl[h]));
}
__device__ __forceinline__ uint32_t f2tf32(float x){
    uint32_t r; asm("cvt.rna.tf32.f32 %0, %1;" : "=r"(r) : "f"(x)); return r;
}
__device__ __forceinline__ float round_tf32(float x){
    return __uint_as_float(f2tf32(x));
}
__device__ __forceinline__ void mma_tf32(float* c, const uint4& a, const uint2& b){
    asm volatile("mma.sync.aligned.m16n8k8.row.col.f32.tf32.tf32.f32 "
        "{%0,%1,%2,%3}, {%4,%5,%6,%7}, {%8,%9}, {%0,%1,%2,%3};"
        : "+f"(c[0]), "+f"(c[1]), "+f"(c[2]), "+f"(c[3])
        : "r"(a.x), "r"(a.y), "r"(a.z), "r"(a.w), "r"(b.x), "r"(b.y));
}
// fragment-pack index helpers (m16n8k8 tf32)
__device__ __forceinline__ int Aidx(int KS, int r, int k){
    return (((r>>4)*KS + (k>>3))*32 + (r&7)*4 + (k&3))*4 + ((r>>3)&1) + 2*((k>>2)&1);
}
__device__ __forceinline__ int Bidx(int KS, int n, int k){
    return (((n>>3)*KS + (k>>3))*32 + (n&7)*4 + (k&3))*2 + ((k>>2)&1);
}

// ------- fused W transpose + tf32 pre-round: Wt[n][k] = round(W[k][n]) ------
__global__ void transpose_kernel(const float* __restrict__ Wq,
                                 const float* __restrict__ Wo)
{
    __shared__ float tile[32][33];
    int bx = blockIdx.x;
    const float* W; float* Wt; int N;
    if (bx < 48){ W = Wq; Wt = g_WqkvT; N = 3*DM; }
    else        { bx -= 48; W = Wo; Wt = g_WoutT; N = DM; }
    const int n0 = bx*32, k0 = blockIdx.y*32;
    const int tx = threadIdx.x, ty = threadIdx.y;   // 32 x 8
    #pragma unroll
    for (int j=0;j<32;j+=8)
        tile[ty+j][tx] = W[(size_t)(k0+ty+j)*N + n0+tx];
    __syncthreads();
    #pragma unroll
    for (int j=0;j<32;j+=8)
        Wt[(size_t)(n0+ty+j)*DM + k0+tx] = round_tf32(tile[tx][ty+j]);
}

// =================== tf32 mma.sync GEMM: D = A @ Wt^T + b ===================
template<int MODE>
__global__ __launch_bounds__(256) void mma_gemm_kernel(const float* __restrict__ Ain,
                                                       const float* __restrict__ bias)
{
    extern __shared__ uint32_t sm[];        // 2 bufs x (A 4096 + B 4096) u32
    const float* A  = (MODE==0) ? Ain : g_attn;
    const float* Wt = (MODE==0) ? g_WqkvT : g_WoutT;
    const int m0 = blockIdx.y*128, n0 = blockIdx.x*128;
    const int t = threadIdx.x, lane = t&31, wid = t>>5;
    const int wm = wid&1, wn = wid>>1;

    const int c4    = (t&7)<<2;
    const int kkL   = c4>>3;
    const int cregL = (c4>>2)&1;
    const int rlo   = t>>3;
    const int lane0 = (rlo&7)<<2;
    const int rhi   = (t>>6)&1;
    const int mt0   = t>>7;
    const int nt0   = (t>>6)&3;
    const int regA  = rhi + 2*cregL;

    float4 ra[4], rb[4];
    float acc[4][4][4];
    #pragma unroll
    for (int i=0;i<4;i++)
        #pragma unroll
        for (int j=0;j<4;j++)
            #pragma unroll
            for (int r=0;r<4;r++) acc[i][j][r]=0.f;

    auto ldg = [&](int c){
        const int k0 = c*32;
        #pragma unroll
        for (int i=0;i<4;i++){
            ra[i] = *(const float4*)&A [(size_t)(m0 + rlo + 32*i)*DM + k0 + c4];
            rb[i] = *(const float4*)&Wt[(size_t)(n0 + rlo + 32*i)*DM + k0 + c4];
        }
    };
    auto cvtA = [&](float x)->uint32_t {
        return (MODE==0) ? f2tf32(x) : __float_as_uint(x);
    };
    auto sts = [&](int buf){
        uint32_t* Ab = sm + buf*8192;
        uint32_t* Bb = Ab + 4096;
        #pragma unroll
        for (int i=0;i<4;i++){
            const int mt = mt0 + 2*i;
            const uint32_t ab = (uint32_t)(((mt*4 + kkL)*32 + lane0)*4 + regA);
            Ab[ab + 0*4] = cvtA(ra[i].x);
            Ab[ab + 1*4] = cvtA(ra[i].y);
            Ab[ab + 2*4] = cvtA(ra[i].z);
            Ab[ab + 3*4] = cvtA(ra[i].w);
            const int nt = nt0 + 4*i;
            const uint32_t bb = (uint32_t)(((nt*4 + kkL)*32 + lane0)*2 + cregL);
            Bb[bb + 0*2] = __float_as_uint(rb[i].x);
            Bb[bb + 1*2] = __float_as_uint(rb[i].y);
            Bb[bb + 2*2] = __float_as_uint(rb[i].z);
            Bb[bb + 3*2] = __float_as_uint(rb[i].w);
        }
    };
    auto compute = [&](int buf){
        const uint32_t* Ab = sm + buf*8192;
        const uint32_t* Bb = Ab + 4096;
        #pragma unroll
        for (int kk=0;kk<4;kk++){
            uint4 a[4]; uint2 b[4];
            #pragma unroll
            for (int i=0;i<4;i++)
                a[i] = *(const uint4*)&Ab[(((wm*4+i)*4+kk)*32 + lane)*4];
            #pragma unroll
            for (int j=0;j<4;j++)
                b[j] = *(const uint2*)&Bb[(((wn*4+j)*4+kk)*32 + lane)*2];
            #pragma unroll
            for (int i=0;i<4;i++)
                #pragma unroll
                for (int j=0;j<4;j++)
                    mma_tf32(acc[i][j], a[i], b[j]);
        }
    };

    ldg(0); sts(0); __syncthreads();
    #pragma unroll 1
    for (int c=0;c<16;c++){
        if (c<15) ldg(c+1);
        compute(c&1);
        if (c<15) sts((c+1)&1);
        __syncthreads();
    }

    int regi = 0; float* dst;
    if (MODE==0){
        regi = n0 >> 9;
        dst = (regi==0) ? g_q : (regi==1) ? g_k : g_v;
    } else dst = g_y;
    const int nsub = (MODE==0) ? (n0 - regi*512) : n0;
    const int rowl = lane>>2, colp = (lane&3)*2;

    #pragma unroll
    for (int i=0;i<4;i++){
        #pragma unroll
        for (int j=0;j<4;j++){
            const int nn = n0   + wn*32 + j*8 + colp;
            const int nc = nsub + wn*32 + j*8 + colp;
            const float b0v = __ldg(&bias[nn]);
            const float b1v = __ldg(&bias[nn+1]);
            float v[4] = { acc[i][j][0] + b0v, acc[i][j][1] + b1v,
                           acc[i][j][2] + b0v, acc[i][j][3] + b1v };
            if (MODE==0){
                if (regi==0){
                    #pragma unroll
                    for (int e=0;e<4;e++){ float x=(v[e]>0.f)?v[e]+1.f:expf(v[e]); v[e]=round_tf32(x*0.125f); }
                } else if (regi==1){
                    #pragma unroll
                    for (int e=0;e<4;e++){ float x=(v[e]>0.f)?v[e]+1.f:expf(v[e]); v[e]=round_tf32(x); }
                } else {
                    #pragma unroll
                    for (int e=0;e<4;e++) v[e]=round_tf32(v[e]);
                }
            }
            const int r0 = m0 + wm*64 + i*16 + rowl;
            *(float2*)&dst[(size_t)r0*DM + nc]     = make_float2(v[0], v[1]);
            *(float2*)&dst[(size_t)(r0+8)*DM + nc] = make_float2(v[2], v[3]);
        }
    }
}

// ============== chunk_local via mma: S_loc = (pw*K)^T @ V,  64x64x128 =======
__global__ __launch_bounds__(256) void chunk_local_kernel(const float* __restrict__ dl)
{
    extern __shared__ uint32_t sl[];
    uint32_t* Aa = sl;            // A-pack 64x128 (KS=16) : 8192 u32
    uint32_t* Bb = sl + 8192;     // B-pack 64x128 (KS=16) : 8192 u32
    __shared__ float pw[128];
    __shared__ float zpart[4][64];

    const int c = blockIdx.x, bh = blockIdx.y;
    const int b = bh / NH, h = bh % NH;
    const int t = threadIdx.x, lane = t&31, wid = t>>5;
    const int wm = wid&1, wn = wid>>1;
    const int g = lane>>2, tg = lane&3;
    const float lam = lam_of(dl, h);
    if (t < 128) pw[t] = exp2f((float)t * log2f(lam));
    __syncthreads();

    const size_t rowbase = ((size_t)b*SL + (size_t)c*CK)*DM + h*ED;
    for (int vi = t; vi < 2048; vi += 256){
        const int j = vi >> 4, e4 = (vi & 15)*4;
        const float w = pw[127-j];
        float4 kv = *(const float4*)&g_k[rowbase + (size_t)j*DM + e4];
        Aa[Aidx(16, e4+0, j)] = f2tf32(w*kv.x);
        Aa[Aidx(16, e4+1, j)] = f2tf32(w*kv.y);
        Aa[Aidx(16, e4+2, j)] = f2tf32(w*kv.z);
        Aa[Aidx(16, e4+3, j)] = f2tf32(w*kv.w);
        float4 vv = *(const float4*)&g_v[rowbase + (size_t)j*DM + e4];
        Bb[Bidx(16, e4+0, j)] = __float_as_uint(vv.x);
        Bb[Bidx(16, e4+1, j)] = __float_as_uint(vv.y);
        Bb[Bidx(16, e4+2, j)] = __float_as_uint(vv.z);
        Bb[Bidx(16, e4+3, j)] = __float_as_uint(vv.w);
    }
    {
        const int e = t & 63, part = t >> 6;
        float z = 0.f;
        #pragma unroll 4
        for (int j = part*32; j < part*32+32; j++)
            z += pw[127-j] * g_k[rowbase + (size_t)j*DM + e];
        zpart[part][e] = z;
    }
    __syncthreads();
    if (t < ED)
        g_zloc[((size_t)bh*NCH + c)*ED + t] =
            zpart[0][t] + zpart[1][t] + zpart[2][t] + zpart[3][t];

    float acc[2][2][4];
    #pragma unroll
    for (int i=0;i<2;i++)
        #pragma unroll
        for (int j=0;j<2;j++)
            #pragma unroll
            for (int r=0;r<4;r++) acc[i][j][r]=0.f;
    #pragma unroll
    for (int kk=0;kk<16;kk++){
        uint4 a[2]; uint2 b2[2];
        #pragma unroll
        for (int i=0;i<2;i++)
            a[i] = *(const uint4*)&Aa[(((wm*2+i)*16+kk)*32 + lane)*4];
        #pragma unroll
        for (int j=0;j<2;j++)
            b2[j] = *(const uint2*)&Bb[(((wn*2+j)*16+kk)*32 + lane)*2];
        #pragma unroll
        for (int i=0;i<2;i++)
            #pragma unroll
            for (int j=0;j<2;j++)
                mma_tf32(acc[i][j], a[i], b2[j]);
    }
    const size_t sb = ((size_t)bh*NCH + c)*ED*ED;
    #pragma unroll
    for (int i=0;i<2;i++){
        #pragma unroll
        for (int j=0;j<2;j++){
            const int e0 = wm*32 + i*16 + g;
            const int f0 = wn*16 + j*8 + tg*2;
            *(float2*)&g_Sloc[sb + e0*ED + f0]     = make_float2(acc[i][j][0], acc[i][j][1]);
            *(float2*)&g_Sloc[sb + (e0+8)*ED + f0] = make_float2(acc[i][j][2], acc[i][j][3]);
        }
    }
}

// ----- PARALLEL inter-chunk scan: one thread per state element -------------
// grid (NBH, 16 segments) x 256 thr; prefetch all 16 chunk values (MLP=16),
// register scan, coalesced stores. z folded into segment 0.
__global__ __launch_bounds__(256) void scan_kernel(const float* __restrict__ dl)
{
    const int bh  = blockIdx.x;
    const int el  = blockIdx.y*256 + threadIdx.x;    // 0..4095
    const int h   = bh % NH;
    const float lam  = lam_of(dl, h);
    const float lamC = exp2f((float)CK * log2f(lam));
    const size_t base = (size_t)bh*NCH*ED*ED + el;

    float v[NCH];
    #pragma unroll
    for (int c=0;c<NCH;c++) v[c] = g_Sloc[base + (size_t)c*ED*ED];
    float s = 0.f;
    #pragma unroll
    for (int c=0;c<NCH;c++){
        g_Sin[base + (size_t)c*ED*ED] = s;
        s = lamC*s + v[c];
    }

    if (blockIdx.y == 0 && threadIdx.x < ED){
        const size_t zb = (size_t)bh*NCH*ED + threadIdx.x;
        float zv[NCH];
        #pragma unroll
        for (int c=0;c<NCH;c++) zv[c] = g_zloc[zb + (size_t)c*ED];
        float z = 0.f;
        #pragma unroll
        for (int c=0;c<NCH;c++){
            g_zin[zb + (size_t)c*ED] = z;
            z = lamC*z + zv[c];
        }
    }
}

// ================= chunk_out via mma =======================================
__global__ __launch_bounds__(256) void chunk_out_kernel(const float* __restrict__ dl)
{
    extern __shared__ uint32_t su[];
    uint32_t* Qa = su;             // A-pack Q  128x64  (KS=8)  : 8192
    uint32_t* Kb = Qa + 8192;      // B-pack K  n=128,k=64      : 8192
    uint32_t* Pa = Kb + 8192;      // A-pack P  128x128 (KS=16) : 16384
    uint32_t* Vb = Pa + 16384;     // B-pack V^T n=64,k=128     : 8192
    uint32_t* Sb = Vb + 8192;      // B-pack S^T n=64,k=64      : 4096
    __shared__ float pw[132];
    __shared__ float dens2[4][128];
    __shared__ float dens[128];
    __shared__ float dq2[2][128];
    __shared__ float dqs[128];
    __shared__ float zs[64];

    const int c = blockIdx.x, bh = blockIdx.y;
    const int b = bh / NH, h = bh % NH;
    const int t = threadIdx.x, lane = t&31, wid = t>>5;
    const int wm = wid&1, wn = wid>>1;
    const int g = lane>>2, tg = lane&3;
    const float lam = lam_of(dl, h);
    if (t <= 128) pw[t] = exp2f((float)t * log2f(lam));
    if (t < ED)   zs[t] = g_zin[((size_t)bh*NCH+c)*ED + t];

    const size_t rowbase = ((size_t)b*SL + (size_t)c*CK)*DM + h*ED;
    for (int idx = t; idx < 8192; idx += 256){
        const int r = idx >> 6, k = idx & 63;
        Qa[Aidx(8, r, k)] = __float_as_uint(g_q[rowbase + (size_t)r*DM + k]);
        Kb[Bidx(8, r, k)] = __float_as_uint(g_k[rowbase + (size_t)r*DM + k]);
        Vb[Bidx(16, idx & 63, idx >> 6)] = __float_as_uint(g_v[rowbase + (size_t)(idx>>6)*DM + (idx&63)]);
    }
    {
        const size_t sbase = ((size_t)bh*NCH + c)*ED*ED;
        for (int idx = t; idx < 4096; idx += 256){
            const int e = idx >> 6, f = idx & 63;
            Sb[Bidx(8, f, e)] = f2tf32(g_Sin[sbase + idx]);
        }
    }
    __syncthreads();

    {
        const int row = t & 127, half = t >> 7;
        float q = 0.f;
        #pragma unroll 4
        for (int e = half*32; e < half*32+32; e++)
            q += g_q[rowbase + (size_t)row*DM + e] * zs[e];
        dq2[half][row] = q;
    }

    float accP[4][4][4];
    #pragma unroll
    for (int i=0;i<4;i++)
        #pragma unroll
        for (int j=0;j<4;j++)
            #pragma unroll
            for (int r=0;r<4;r++) accP[i][j][r]=0.f;
    #pragma unroll
    for (int kk=0;kk<8;kk++){
        uint4 a[4]; uint2 b2[4];
        #pragma unroll
        for (int i=0;i<4;i++)
            a[i] = *(const uint4*)&Qa[(((wm*4+i)*8+kk)*32 + lane)*4];
        #pragma unroll
        for (int j=0;j<4;j++)
            b2[j] = *(const uint2*)&Kb[(((wn*4+j)*8+kk)*32 + lane)*2];
        #pragma unroll
        for (int i=0;i<4;i++)
            #pragma unroll
            for (int j=0;j<4;j++)
                mma_tf32(accP[i][j], a[i], b2[j]);
    }

    #pragma unroll
    for (int i=0;i<4;i++){
        float rs_lo = 0.f, rs_hi = 0.f;
        const int ii_lo = wm*64 + i*16 + g;
        const int ii_hi = ii_lo + 8;
        #pragma unroll
        for (int j=0;j<4;j++){
            #pragma unroll
            for (int r=0;r<4;r++){
                const int ii = (r<2) ? ii_lo : ii_hi;
                const int jj = wn*32 + j*8 + tg*2 + (r&1);
                const float w = (jj <= ii) ? pw[ii-jj] : 0.f;
                const float val = w * accP[i][j][r];
                Pa[Aidx(16, ii, jj)] = f2tf32(val);
                if (r<2) rs_lo += val; else rs_hi += val;
            }
        }
        rs_lo += __shfl_down_sync(0xffffffffu, rs_lo, 2, 4);
        rs_lo += __shfl_down_sync(0xffffffffu, rs_lo, 1, 4);
        rs_hi += __shfl_down_sync(0xffffffffu, rs_hi, 2, 4);
        rs_hi += __shfl_down_sync(0xffffffffu, rs_hi, 1, 4);
        if (tg == 0){
            dens2[wn][ii_lo] = rs_lo;
            dens2[wn][ii_hi] = rs_hi;
        }
    }
    __syncthreads();

    if (t < 128){
        dens[t] = dens2[0][t] + dens2[1][t] + dens2[2][t] + dens2[3][t];
        dqs[t]  = dq2[0][t] + dq2[1][t];
    }

    float acc1[4][2][4], acc2[4][2][4];
    #pragma unroll
    for (int i=0;i<4;i++)
        #pragma unroll
        for (int j=0;j<2;j++)
            #pragma unroll
            for (int r=0;r<4;r++){ acc1[i][j][r]=0.f; acc2[i][j][r]=0.f; }
    #pragma unroll
    for (int kk=0;kk<8;kk++){
        uint4 a[4]; uint2 b2[2];
        #pragma unroll
        for (int i=0;i<4;i++)
            a[i] = *(const uint4*)&Qa[(((wm*4+i)*8+kk)*32 + lane)*4];
        #pragma unroll
        for (int j=0;j<2;j++)
            b2[j] = *(const uint2*)&Sb[(((wn*2+j)*8+kk)*32 + lane)*2];
        #pragma unroll
        for (int i=0;i<4;i++)
            #pragma unroll
            for (int j=0;j<2;j++)
                mma_tf32(acc1[i][j], a[i], b2[j]);
    }
    #pragma unroll
    for (int kk=0;kk<16;kk++){
        uint4 a[4]; uint2 b2[2];
        #pragma unroll
        for (int i=0;i<4;i++)
            a[i] = *(const uint4*)&Pa[(((wm*4+i)*16+kk)*32 + lane)*4];
        #pragma unroll
        for (int j=0;j<2;j++)
            b2[j] = *(const uint2*)&Vb[(((wn*2+j)*16+kk)*32 + lane)*2];
        #pragma unroll
        for (int i=0;i<4;i++)
            #pragma unroll
            for (int j=0;j<2;j++)
                mma_tf32(acc2[i][j], a[i], b2[j]);
    }
    __syncthreads();

    const int mrow = b*SL + c*CK;
    #pragma unroll
    for (int i=0;i<4;i++){
        const int ii_lo = wm*64 + i*16 + g;
        #pragma unroll
        for (int rr=0;rr<2;rr++){
            const int ii = ii_lo + rr*8;
            const float pwi = pw[ii+1];
            const float inv = 1.f / (pwi*dqs[ii] + dens[ii] + 1e-6f);
            #pragma unroll
            for (int j=0;j<2;j++){
                const int f0 = wn*16 + j*8 + tg*2;
                const float v0 = round_tf32((pwi*acc1[i][j][rr*2+0] + acc2[i][j][rr*2+0])*inv);
                const float v1 = round_tf32((pwi*acc1[i][j][rr*2+1] + acc2[i][j][rr*2+1])*inv);
                *(float2*)&g_attn[(size_t)(mrow+ii)*DM + h*ED + f0] = make_float2(v0, v1);
            }
        }
    }
}

// ---------------- LayerNorm ------------------------------------------------
__global__ __launch_bounds__(128) void ln_kernel(const float* __restrict__ gg,
                                                 const float* __restrict__ bb,
                                                 float* __restrict__ out)
{
    const int row = blockIdx.x, t = threadIdx.x;
    __shared__ float red[8];
    float4 v = *(const float4*)&g_y[(size_t)row*DM + t*4];
    float s  = v.x+v.y+v.z+v.w;
    float s2 = v.x*v.x+v.y*v.y+v.z*v.z+v.w*v.w;
    #pragma unroll
    for (int o=16;o;o>>=1){
        s  += __shfl_xor_sync(0xffffffffu, s,  o);
        s2 += __shfl_xor_sync(0xffffffffu, s2, o);
    }
    const int w = t>>5;
    if ((t&31)==0){ red[w]=s; red[4+w]=s2; }
    __syncthreads();
    s  = red[0]+red[1]+red[2]+red[3];
    s2 = red[4]+red[5]+red[6]+red[7];
    const float mean = s*(1.0f/DM);
    const float var  = s2*(1.0f/DM) - mean*mean;
    const float inv  = rsqrtf(var + 1e-5f);
    float4 gv = *(const float4*)&gg[t*4];
    float4 bv = *(const float4*)&bb[t*4];
    float4 o;
    o.x = (v.x-mean)*inv*gv.x + bv.x;
    o.y = (v.y-mean)*inv*gv.y + bv.y;
    o.z = (v.z-mean)*inv*gv.z + bv.z;
    o.w = (v.w-mean)*inv*gv.w + bv.w;
    *(float4*)&out[(size_t)row*DM + t*4] = o;
}

// ---------------- launch ----------------------------------------------------
extern "C" void kernel_launch(void* const* d_in, const int* in_sizes, int n_in,
                              void* d_out, int out_size)
{
    const float* x     = (const float*)d_in[0];
    const float* W_qkv = (const float*)d_in[1];
    const float* b_qkv = (const float*)d_in[2];
    const float* W_out = (const float*)d_in[3];
    const float* b_out = (const float*)d_in[4];
    const float* dl    = (const float*)d_in[5];
    const float* ln_g  = (const float*)d_in[6];
    const float* ln_b  = (const float*)d_in[7];
    float* out = (float*)d_out;

    const int smem_cl = 16384*4;                                  // 65536 B
    const int smem_co = 45056*4;                                  // 180224 B
    const int smem_mm = 2*8192*4;                                 // 65536 B
    cudaFuncSetAttribute(chunk_local_kernel,
                         cudaFuncAttributeMaxDynamicSharedMemorySize, smem_cl);
    cudaFuncSetAttribute(chunk_out_kernel,
                         cudaFuncAttributeMaxDynamicSharedMemorySize, smem_co);
    cudaFuncSetAttribute(mma_gemm_kernel<0>,
                         cudaFuncAttributeMaxDynamicSharedMemorySize, smem_mm);
    cudaFuncSetAttribute(mma_gemm_kernel<1>,
                         cudaFuncAttributeMaxDynamicSharedMemorySize, smem_mm);

    transpose_kernel<<<dim3(64,16), dim3(32,8)>>>(W_qkv, W_out);
    mma_gemm_kernel<0><<<dim3(12,32), 256, smem_mm>>>(x, b_qkv);
    chunk_local_kernel<<<dim3(NCH,NBH),256,smem_cl>>>(dl);
    scan_kernel<<<dim3(NBH,16),256>>>(dl);
    chunk_out_kernel<<<dim3(NCH,NBH),256,smem_co>>>(dl);
    mma_gemm_kernel<1><<<dim3(4,32), 256, smem_mm>>>(nullptr, b_out);
    ln_kernel<<<MT,128>>>(ln_g, ln_b, out);
}

// round 9
// speedup vs baseline: 1.2365x; 1.1366x over previous
#include <cuda_runtime.h>
#include <math.h>
#include <stdint.h>

#define DM 512
#define NH 8
#define ED 64
#define NB 2
#define SL 2048
#define MT (NB*SL)          // 4096 rows
#define NBH (NB*NH)         // 16 sequences
#define CK 128              // chunk length
#define NCH (SL/CK)         // 16 chunks

// ---------------- scratch (static device globals; no runtime alloc) --------
__device__ float g_q[MT*DM];
__device__ float g_k[MT*DM];
__device__ float g_v[MT*DM];
__device__ float g_attn[MT*DM];
__device__ float g_y[MT*DM];
__device__ float g_WqkvT[3*DM*DM];   // [1536][512], tf32-rounded
__device__ float g_WoutT[DM*DM];     // [512][512],  tf32-rounded
__device__ float g_Sloc[NBH*NCH*ED*ED];
__device__ float g_Sin [NBH*NCH*ED*ED];   // row-major carry-in states [e][f]
__device__ float g_zloc[NBH*NCH*ED];
__device__ float g_zin [NBH*NCH*ED];

__device__ __forceinline__ float lam_of(const float* dl, int h){
    return 0.99f + 0.01f/(1.0f + expf(-dl[h]));
}
__device__ __forceinline__ uint32_t f2tf32(float x){
    uint32_t r; asm("cvt.rna.tf32.f32 %0, %1;" : "=r"(r) : "f"(x)); return r;
}
__device__ __forceinline__ float round_tf32(float x){
    return __uint_as_float(f2tf32(x));
}
__device__ __forceinline__ void mma_tf32(float* c, const uint4& a, const uint2& b){
    asm volatile("mma.sync.aligned.m16n8k8.row.col.f32.tf32.tf32.f32 "
        "{%0,%1,%2,%3}, {%4,%5,%6,%7}, {%8,%9}, {%0,%1,%2,%3};"
        : "+f"(c[0]), "+f"(c[1]), "+f"(c[2]), "+f"(c[3])
        : "r"(a.x), "r"(a.y), "r"(a.z), "r"(a.w), "r"(b.x), "r"(b.y));
}
// fragment-pack index helpers (m16n8k8 tf32)
__device__ __forceinline__ int Aidx(int KS, int r, int k){
    return (((r>>4)*KS + (k>>3))*32 + (r&7)*4 + (k&3))*4 + ((r>>3)&1) + 2*((k>>2)&1);
}
__device__ __forceinline__ int Bidx(int KS, int n, int k){
    return (((n>>3)*KS + (k>>3))*32 + (n&7)*4 + (k&3))*2 + ((k>>2)&1);
}

// ------- fused W transpose + tf32 pre-round: Wt[n][k] = round(W[k][n]) ------
__global__ void transpose_kernel(const float* __restrict__ Wq,
                                 const float* __restrict__ Wo)
{
    __shared__ float tile[32][33];
    int bx = blockIdx.x;
    const float* W; float* Wt; int N;
    if (bx < 48){ W = Wq; Wt = g_WqkvT; N = 3*DM; }
    else        { bx -= 48; W = Wo; Wt = g_WoutT; N = DM; }
    const int n0 = bx*32, k0 = blockIdx.y*32;
    const int tx = threadIdx.x, ty = threadIdx.y;   // 32 x 8
    #pragma unroll
    for (int j=0;j<32;j+=8)
        tile[ty+j][tx] = W[(size_t)(k0+ty+j)*N + n0+tx];
    __syncthreads();
    #pragma unroll
    for (int j=0;j<32;j+=8)
        Wt[(size_t)(n0+ty+j)*DM + k0+tx] = round_tf32(tile[tx][ty+j]);
}

// =================== tf32 mma.sync GEMM: D = A @ Wt^T + b ===================
template<int MODE>
__global__ __launch_bounds__(256) void mma_gemm_kernel(const float* __restrict__ Ain,
                                                       const float* __restrict__ bias)
{
    extern __shared__ uint32_t sm[];        // 2 bufs x (A 4096 + B 4096) u32
    const float* A  = (MODE==0) ? Ain : g_attn;
    const float* Wt = (MODE==0) ? g_WqkvT : g_WoutT;
    const int m0 = blockIdx.y*128, n0 = blockIdx.x*128;
    const int t = threadIdx.x, lane = t&31, wid = t>>5;
    const int wm = wid&1, wn = wid>>1;

    const int c4    = (t&7)<<2;
    const int kkL   = c4>>3;
    const int cregL = (c4>>2)&1;
    const int rlo   = t>>3;
    const int lane0 = (rlo&7)<<2;
    const int rhi   = (t>>6)&1;
    const int mt0   = t>>7;
    const int nt0   = (t>>6)&3;
    const int regA  = rhi + 2*cregL;

    float4 ra[4], rb[4];
    float acc[4][4][4];
    #pragma unroll
    for (int i=0;i<4;i++)
        #pragma unroll
        for (int j=0;j<4;j++)
            #pragma unroll
            for (int r=0;r<4;r++) acc[i][j][r]=0.f;

    auto ldg = [&](int c){
        const int k0 = c*32;
        #pragma unroll
        for (int i=0;i<4;i++){
            ra[i] = *(const float4*)&A [(size_t)(m0 + rlo + 32*i)*DM + k0 + c4];
            rb[i] = *(const float4*)&Wt[(size_t)(n0 + rlo + 32*i)*DM + k0 + c4];
        }
    };
    auto cvtA = [&](float x)->uint32_t {
        return (MODE==0) ? f2tf32(x) : __float_as_uint(x);
    };
    auto sts = [&](int buf){
        uint32_t* Ab = sm + buf*8192;
        uint32_t* Bb = Ab + 4096;
        #pragma unroll
        for (int i=0;i<4;i++){
            const int mt = mt0 + 2*i;
            const uint32_t ab = (uint32_t)(((mt*4 + kkL)*32 + lane0)*4 + regA);
            Ab[ab + 0*4] = cvtA(ra[i].x);
            Ab[ab + 1*4] = cvtA(ra[i].y);
            Ab[ab + 2*4] = cvtA(ra[i].z);
            Ab[ab + 3*4] = cvtA(ra[i].w);
            const int nt = nt0 + 4*i;
            const uint32_t bb = (uint32_t)(((nt*4 + kkL)*32 + lane0)*2 + cregL);
            Bb[bb + 0*2] = __float_as_uint(rb[i].x);
            Bb[bb + 1*2] = __float_as_uint(rb[i].y);
            Bb[bb + 2*2] = __float_as_uint(rb[i].z);
            Bb[bb + 3*2] = __float_as_uint(rb[i].w);
        }
    };
    auto compute = [&](int buf){
        const uint32_t* Ab = sm + buf*8192;
        const uint32_t* Bb = Ab + 4096;
        #pragma unroll
        for (int kk=0;kk<4;kk++){
            uint4 a[4]; uint2 b[4];
            #pragma unroll
            for (int i=0;i<4;i++)
                a[i] = *(const uint4*)&Ab[(((wm*4+i)*4+kk)*32 + lane)*4];
            #pragma unroll
            for (int j=0;j<4;j++)
                b[j] = *(const uint2*)&Bb[(((wn*4+j)*4+kk)*32 + lane)*2];
            #pragma unroll
            for (int i=0;i<4;i++)
                #pragma unroll
                for (int j=0;j<4;j++)
                    mma_tf32(acc[i][j], a[i], b[j]);
        }
    };

    ldg(0); sts(0); __syncthreads();
    #pragma unroll 1
    for (int c=0;c<16;c++){
        if (c<15) ldg(c+1);
        compute(c&1);
        if (c<15) sts((c+1)&1);
        __syncthreads();
    }

    int regi = 0; float* dst;
    if (MODE==0){
        regi = n0 >> 9;
        dst = (regi==0) ? g_q : (regi==1) ? g_k : g_v;
    } else dst = g_y;
    const int nsub = (MODE==0) ? (n0 - regi*512) : n0;
    const int rowl = lane>>2, colp = (lane&3)*2;

    #pragma unroll
    for (int i=0;i<4;i++){
        #pragma unroll
        for (int j=0;j<4;j++){
            const int nn = n0   + wn*32 + j*8 + colp;
            const int nc = nsub + wn*32 + j*8 + colp;
            const float b0v = __ldg(&bias[nn]);
            const float b1v = __ldg(&bias[nn+1]);
            float v[4] = { acc[i][j][0] + b0v, acc[i][j][1] + b1v,
                           acc[i][j][2] + b0v, acc[i][j][3] + b1v };
            if (MODE==0){
                if (regi==0){
                    #pragma unroll
                    for (int e=0;e<4;e++){ float x=(v[e]>0.f)?v[e]+1.f:expf(v[e]); v[e]=round_tf32(x*0.125f); }
                } else if (regi==1){
                    #pragma unroll
                    for (int e=0;e<4;e++){ float x=(v[e]>0.f)?v[e]+1.f:expf(v[e]); v[e]=round_tf32(x); }
                } else {
                    #pragma unroll
                    for (int e=0;e<4;e++) v[e]=round_tf32(v[e]);
                }
            }
            const int r0 = m0 + wm*64 + i*16 + rowl;
            *(float2*)&dst[(size_t)r0*DM + nc]     = make_float2(v[0], v[1]);
            *(float2*)&dst[(size_t)(r0+8)*DM + nc] = make_float2(v[2], v[3]);
        }
    }
}

// ============== chunk_local via mma: S_loc = (pw*K)^T @ V,  64x64x128 =======
__global__ __launch_bounds__(256) void chunk_local_kernel(const float* __restrict__ dl)
{
    extern __shared__ uint32_t sl[];
    uint32_t* Aa = sl;            // A-pack 64x128 (KS=16) : 8192 u32
    uint32_t* Bb = sl + 8192;     // B-pack 64x128 (KS=16) : 8192 u32
    __shared__ float pw[128];
    __shared__ float zpart[4][64];

    const int c = blockIdx.x, bh = blockIdx.y;
    const int b = bh / NH, h = bh % NH;
    const int t = threadIdx.x, lane = t&31, wid = t>>5;
    const int wm = wid&1, wn = wid>>1;
    const int g = lane>>2, tg = lane&3;
    const float lam = lam_of(dl, h);
    if (t < 128) pw[t] = exp2f((float)t * log2f(lam));
    __syncthreads();

    const size_t rowbase = ((size_t)b*SL + (size_t)c*CK)*DM + h*ED;
    for (int vi = t; vi < 2048; vi += 256){
        const int j = vi >> 4, e4 = (vi & 15)*4;
        const float w = pw[127-j];
        float4 kv = *(const float4*)&g_k[rowbase + (size_t)j*DM + e4];
        Aa[Aidx(16, e4+0, j)] = f2tf32(w*kv.x);
        Aa[Aidx(16, e4+1, j)] = f2tf32(w*kv.y);
        Aa[Aidx(16, e4+2, j)] = f2tf32(w*kv.z);
        Aa[Aidx(16, e4+3, j)] = f2tf32(w*kv.w);
        float4 vv = *(const float4*)&g_v[rowbase + (size_t)j*DM + e4];
        Bb[Bidx(16, e4+0, j)] = __float_as_uint(vv.x);
        Bb[Bidx(16, e4+1, j)] = __float_as_uint(vv.y);
        Bb[Bidx(16, e4+2, j)] = __float_as_uint(vv.z);
        Bb[Bidx(16, e4+3, j)] = __float_as_uint(vv.w);
    }
    {
        const int e = t & 63, part = t >> 6;
        float z = 0.f;
        #pragma unroll 4
        for (int j = part*32; j < part*32+32; j++)
            z += pw[127-j] * g_k[rowbase + (size_t)j*DM + e];
        zpart[part][e] = z;
    }
    __syncthreads();
    if (t < ED)
        g_zloc[((size_t)bh*NCH + c)*ED + t] =
            zpart[0][t] + zpart[1][t] + zpart[2][t] + zpart[3][t];

    float acc[2][2][4];
    #pragma unroll
    for (int i=0;i<2;i++)
        #pragma unroll
        for (int j=0;j<2;j++)
            #pragma unroll
            for (int r=0;r<4;r++) acc[i][j][r]=0.f;
    #pragma unroll
    for (int kk=0;kk<16;kk++){
        uint4 a[2]; uint2 b2[2];
        #pragma unroll
        for (int i=0;i<2;i++)
            a[i] = *(const uint4*)&Aa[(((wm*2+i)*16+kk)*32 + lane)*4];
        #pragma unroll
        for (int j=0;j<2;j++)
            b2[j] = *(const uint2*)&Bb[(((wn*2+j)*16+kk)*32 + lane)*2];
        #pragma unroll
        for (int i=0;i<2;i++)
            #pragma unroll
            for (int j=0;j<2;j++)
                mma_tf32(acc[i][j], a[i], b2[j]);
    }
    const size_t sb = ((size_t)bh*NCH + c)*ED*ED;
    #pragma unroll
    for (int i=0;i<2;i++){
        #pragma unroll
        for (int j=0;j<2;j++){
            const int e0 = wm*32 + i*16 + g;
            const int f0 = wn*16 + j*8 + tg*2;
            *(float2*)&g_Sloc[sb + e0*ED + f0]     = make_float2(acc[i][j][0], acc[i][j][1]);
            *(float2*)&g_Sloc[sb + (e0+8)*ED + f0] = make_float2(acc[i][j][2], acc[i][j][3]);
        }
    }
}

// ----- PARALLEL inter-chunk scan: one thread per state element -------------
__global__ __launch_bounds__(256) void scan_kernel(const float* __restrict__ dl)
{
    const int bh  = blockIdx.x;
    const int el  = blockIdx.y*256 + threadIdx.x;    // 0..4095
    const int h   = bh % NH;
    const float lam  = lam_of(dl, h);
    const float lamC = exp2f((float)CK * log2f(lam));
    const size_t base = (size_t)bh*NCH*ED*ED + el;

    float v[NCH];
    #pragma unroll
    for (int c=0;c<NCH;c++) v[c] = g_Sloc[base + (size_t)c*ED*ED];
    float s = 0.f;
    #pragma unroll
    for (int c=0;c<NCH;c++){
        g_Sin[base + (size_t)c*ED*ED] = s;
        s = lamC*s + v[c];
    }

    if (blockIdx.y == 0 && threadIdx.x < ED){
        const size_t zb = (size_t)bh*NCH*ED + threadIdx.x;
        float zv[NCH];
        #pragma unroll
        for (int c=0;c<NCH;c++) zv[c] = g_zloc[zb + (size_t)c*ED];
        float z = 0.f;
        #pragma unroll
        for (int c=0;c<NCH;c++){
            g_zin[zb + (size_t)c*ED] = z;
            z = lamC*z + zv[c];
        }
    }
}

// ================= chunk_out: P stays in registers =========================
// warp tile = 16 rows x ALL cols. C-frag -> A-frag via intra-quad shuffles.
__global__ __launch_bounds__(256,2) void chunk_out_kernel(const float* __restrict__ dl)
{
    extern __shared__ uint32_t su[];
    uint32_t* Kb = su;            // B-pack K: n=row j (128), k=e (64), KS=8 : 8192
    uint32_t* Vb = su + 8192;     // B-pack V^T: n=f (64), k=j (128), KS=16 : 8192
    uint32_t* Sb = su + 16384;    // B-pack S^T: n=f (64), k=e (64),  KS=8  : 4096
    __shared__ float pw[132];
    __shared__ float zs[64];

    const int c = blockIdx.x, bh = blockIdx.y;
    const int b = bh / NH, h = bh % NH;
    const int t = threadIdx.x, lane = t&31, wid = t>>5;
    const int g = lane>>2, tg = lane&3;
    const float lam = lam_of(dl, h);
    if (t <= 128) pw[t] = exp2f((float)t * log2f(lam));
    if (t < ED)   zs[t] = g_zin[((size_t)bh*NCH+c)*ED + t];

    const size_t rowbase = ((size_t)b*SL + (size_t)c*CK)*DM + h*ED;
    for (int idx = t; idx < 8192; idx += 256){
        const int r = idx >> 6, k = idx & 63;
        Kb[Bidx(8, r, k)]  = __float_as_uint(g_k[rowbase + (size_t)r*DM + k]);
        Vb[Bidx(16, k, r)] = __float_as_uint(g_v[rowbase + (size_t)r*DM + k]);
    }
    {
        const size_t sbase = ((size_t)bh*NCH + c)*ED*ED;
        for (int idx = t; idx < 4096; idx += 256){
            const int e = idx >> 6, f = idx & 63;
            Sb[Bidx(8, f, e)] = f2tf32(g_Sin[sbase + idx]);
        }
    }
    __syncthreads();

    const int rb    = wid*16;
    const int ii_lo = rb + g, ii_hi = ii_lo + 8;

    // Q A-fragments straight from GMEM (g_q pre-rounded tf32)
    uint4 qf[8];
    #pragma unroll
    for (int kk=0;kk<8;kk++){
        const float* q0 = &g_q[rowbase + (size_t)ii_lo*DM + kk*8];
        const float* q1 = &g_q[rowbase + (size_t)ii_hi*DM + kk*8];
        qf[kk].x = __float_as_uint(q0[tg]);
        qf[kk].y = __float_as_uint(q1[tg]);
        qf[kk].z = __float_as_uint(q0[tg+4]);
        qf[kk].w = __float_as_uint(q1[tg+4]);
    }

    // dqs = q . z_in (quad-reduced; all 4 lanes of quad get full sum)
    float dq_lo = 0.f, dq_hi = 0.f;
    #pragma unroll
    for (int kk=0;kk<8;kk++){
        dq_lo += __uint_as_float(qf[kk].x)*zs[kk*8+tg]
               + __uint_as_float(qf[kk].z)*zs[kk*8+tg+4];
        dq_hi += __uint_as_float(qf[kk].y)*zs[kk*8+tg]
               + __uint_as_float(qf[kk].w)*zs[kk*8+tg+4];
    }
    dq_lo += __shfl_xor_sync(0xffffffffu, dq_lo, 1);
    dq_lo += __shfl_xor_sync(0xffffffffu, dq_lo, 2);
    dq_hi += __shfl_xor_sync(0xffffffffu, dq_hi, 1);
    dq_hi += __shfl_xor_sync(0xffffffffu, dq_hi, 2);

    // acc1 = Q @ S_in  (16 rows x 64 f)
    float acc1[8][4];
    #pragma unroll
    for (int j=0;j<8;j++)
        #pragma unroll
        for (int r=0;r<4;r++) acc1[j][r]=0.f;
    #pragma unroll
    for (int kk=0;kk<8;kk++){
        #pragma unroll
        for (int j=0;j<8;j++){
            uint2 bb = *(const uint2*)&Sb[((j*8+kk)*32 + lane)*2];
            mma_tf32(acc1[j], qf[kk], bb);
        }
    }

    // phase 1: P = Q K^T  (16 rows x 128 cols, all in this warp)
    uint4 accPq[16];
    #pragma unroll
    for (int j=0;j<16;j++) accPq[j] = make_uint4(0,0,0,0);
    #pragma unroll
    for (int kk=0;kk<8;kk++){
        #pragma unroll
        for (int j=0;j<16;j++){
            uint2 bb = *(const uint2*)&Kb[((j*8+kk)*32 + lane)*2];
            mma_tf32((float*)&accPq[j], qf[kk], bb);
        }
    }

    // weight + mask in C-layout; dens row-sums (quad-reduced)
    float dens_lo = 0.f, dens_hi = 0.f;
    #pragma unroll
    for (int j=0;j<16;j++){
        const int jj0 = j*8 + 2*tg;
        const float w00 = (jj0   <= ii_lo) ? pw[ii_lo-jj0]   : 0.f;
        const float w01 = (jj0+1 <= ii_lo) ? pw[ii_lo-jj0-1] : 0.f;
        const float w10 = (jj0   <= ii_hi) ? pw[ii_hi-jj0]   : 0.f;
        const float w11 = (jj0+1 <= ii_hi) ? pw[ii_hi-jj0-1] : 0.f;
        float c0 = w00*__uint_as_float(accPq[j].x);
        float c1 = w01*__uint_as_float(accPq[j].y);
        float c2 = w10*__uint_as_float(accPq[j].z);
        float c3 = w11*__uint_as_float(accPq[j].w);
        accPq[j].x = __float_as_uint(c0);
        accPq[j].y = __float_as_uint(c1);
        accPq[j].z = __float_as_uint(c2);
        accPq[j].w = __float_as_uint(c3);
        dens_lo += c0 + c1;
        dens_hi += c2 + c3;
    }
    dens_lo += __shfl_xor_sync(0xffffffffu, dens_lo, 1);
    dens_lo += __shfl_xor_sync(0xffffffffu, dens_lo, 2);
    dens_hi += __shfl_xor_sync(0xffffffffu, dens_hi, 1);
    dens_hi += __shfl_xor_sync(0xffffffffu, dens_hi, 2);

    // C-frag -> A-frag transform in registers (intra-quad shuffles)
    // C holds cols {2tg, 2tg+1}; A needs cols {tg, tg+4}
    const int srcA = (lane & 28) | (tg>>1);
    const int srcB = srcA + 2;
    const bool odd = (tg & 1);
    #pragma unroll
    for (int j=0;j<16;j++){
        float c0 = __uint_as_float(accPq[j].x);
        float c1 = __uint_as_float(accPq[j].y);
        float c2 = __uint_as_float(accPq[j].z);
        float c3 = __uint_as_float(accPq[j].w);
        float v0a = __shfl_sync(0xffffffffu, c0, srcA);
        float v1a = __shfl_sync(0xffffffffu, c1, srcA);
        float v2a = __shfl_sync(0xffffffffu, c2, srcA);
        float v3a = __shfl_sync(0xffffffffu, c3, srcA);
        float v0b = __shfl_sync(0xffffffffu, c0, srcB);
        float v1b = __shfl_sync(0xffffffffu, c1, srcB);
        float v2b = __shfl_sync(0xffffffffu, c2, srcB);
        float v3b = __shfl_sync(0xffffffffu, c3, srcB);
        accPq[j].x = f2tf32(odd ? v1a : v0a);   // (ii_lo, j*8+tg)
        accPq[j].y = f2tf32(odd ? v3a : v2a);   // (ii_hi, j*8+tg)
        accPq[j].z = f2tf32(odd ? v1b : v0b);   // (ii_lo, j*8+tg+4)
        accPq[j].w = f2tf32(odd ? v3b : v2b);   // (ii_hi, j*8+tg+4)
    }

    // acc2 = P @ V  (16 rows x 64 f, K=128 from registers)
    float acc2[8][4];
    #pragma unroll
    for (int j=0;j<8;j++)
        #pragma unroll
        for (int r=0;r<4;r++) acc2[j][r]=0.f;
    #pragma unroll
    for (int kk=0;kk<16;kk++){
        #pragma unroll
        for (int j=0;j<8;j++){
            uint2 bb = *(const uint2*)&Vb[((j*16+kk)*32 + lane)*2];
            mma_tf32(acc2[j], accPq[kk], bb);
        }
    }

    // final: combine, divide, store (pre-rounded tf32 for mode-1 GEMM)
    const int mrow = b*SL + c*CK;
    const float pw_lo = pw[ii_lo+1], pw_hi = pw[ii_hi+1];
    const float inv_lo = 1.f / (pw_lo*dq_lo + dens_lo + 1e-6f);
    const float inv_hi = 1.f / (pw_hi*dq_hi + dens_hi + 1e-6f);
    #pragma unroll
    for (int j=0;j<8;j++){
        const int f0 = j*8 + 2*tg;
        const float v0 = round_tf32((pw_lo*acc1[j][0] + acc2[j][0])*inv_lo);
        const float v1 = round_tf32((pw_lo*acc1[j][1] + acc2[j][1])*inv_lo);
        const float v2 = round_tf32((pw_hi*acc1[j][2] + acc2[j][2])*inv_hi);
        const float v3 = round_tf32((pw_hi*acc1[j][3] + acc2[j][3])*inv_hi);
        *(float2*)&g_attn[(size_t)(mrow+ii_lo)*DM + h*ED + f0] = make_float2(v0, v1);
        *(float2*)&g_attn[(size_t)(mrow+ii_hi)*DM + h*ED + f0] = make_float2(v2, v3);
    }
}

// ---------------- LayerNorm ------------------------------------------------
__global__ __launch_bounds__(128) void ln_kernel(const float* __restrict__ gg,
                                                 const float* __restrict__ bb,
                                                 float* __restrict__ out)
{
    const int row = blockIdx.x, t = threadIdx.x;
    __shared__ float red[8];
    float4 v = *(const float4*)&g_y[(size_t)row*DM + t*4];
    float s  = v.x+v.y+v.z+v.w;
    float s2 = v.x*v.x+v.y*v.y+v.z*v.z+v.w*v.w;
    #pragma unroll
    for (int o=16;o;o>>=1){
        s  += __shfl_xor_sync(0xffffffffu, s,  o);
        s2 += __shfl_xor_sync(0xffffffffu, s2, o);
    }
    const int w = t>>5;
    if ((t&31)==0){ red[w]=s; red[4+w]=s2; }
    __syncthreads();
    s  = red[0]+red[1]+red[2]+red[3];
    s2 = red[4]+red[5]+red[6]+red[7];
    const float mean = s*(1.0f/DM);
    const float var  = s2*(1.0f/DM) - mean*mean;
    const float inv  = rsqrtf(var + 1e-5f);
    float4 gv = *(const float4*)&gg[t*4];
    float4 bv = *(const float4*)&bb[t*4];
    float4 o;
    o.x = (v.x-mean)*inv*gv.x + bv.x;
    o.y = (v.y-mean)*inv*gv.y + bv.y;
    o.z = (v.z-mean)*inv*gv.z + bv.z;
    o.w = (v.w-mean)*inv*gv.w + bv.w;
    *(float4*)&out[(size_t)row*DM + t*4] = o;
}

// ---------------- launch ----------------------------------------------------
extern "C" void kernel_launch(void* const* d_in, const int* in_sizes, int n_in,
                              void* d_out, int out_size)
{
    const float* x     = (const float*)d_in[0];
    const float* W_qkv = (const float*)d_in[1];
    const float* b_qkv = (const float*)d_in[2];
    const float* W_out = (const float*)d_in[3];
    const float* b_out = (const float*)d_in[4];
    const float* dl    = (const float*)d_in[5];
    const float* ln_g  = (const float*)d_in[6];
    const float* ln_b  = (const float*)d_in[7];
    float* out = (float*)d_out;

    const int smem_cl = 16384*4;                                  // 65536 B
    const int smem_co = 20480*4;                                  // 81920 B
    const int smem_mm = 2*8192*4;                                 // 65536 B
    cudaFuncSetAttribute(chunk_local_kernel,
                         cudaFuncAttributeMaxDynamicSharedMemorySize, smem_cl);
    cudaFuncSetAttribute(chunk_out_kernel,
                         cudaFuncAttributeMaxDynamicSharedMemorySize, smem_co);
    cudaFuncSetAttribute(mma_gemm_kernel<0>,
                         cudaFuncAttributeMaxDynamicSharedMemorySize, smem_mm);
    cudaFuncSetAttribute(mma_gemm_kernel<1>,
                         cudaFuncAttributeMaxDynamicSharedMemorySize, smem_mm);

    transpose_kernel<<<dim3(64,16), dim3(32,8)>>>(W_qkv, W_out);
    mma_gemm_kernel<0><<<dim3(12,32), 256, smem_mm>>>(x, b_qkv);
    chunk_local_kernel<<<dim3(NCH,NBH),256,smem_cl>>>(dl);
    scan_kernel<<<dim3(NBH,16),256>>>(dl);
    chunk_out_kernel<<<dim3(NCH,NBH),256,smem_co>>>(dl);
    mma_gemm_kernel<1><<<dim3(4,32), 256, smem_mm>>>(nullptr, b_out);
    ln_kernel<<<MT,128>>>(ln_g, ln_b, out);
}